// round 15
// baseline (speedup 1.0000x reference)
#include <cuda_runtime.h>
#include <cuda_bf16.h>
#include <math.h>
#include <stdint.h>

#define BATCH 1024
#define NC 32
#define LPRE 1041
#define LH 520
#define L1 257
#define L2 125
#define LP 31
#define LZ 12

// ---------------- scratch (device globals) ------------------------------------------
__device__ float g_h[BATCH * NC * LH];            // pooled RAW conv (pre-BN), 68 MB
__device__ float g_p1[BATCH * NC * LP];
__device__ float g_p2[BATCH * NC * LP];
__device__ float g_psA[NC * BATCH];
__device__ float g_psqA[NC * BATCH];
__device__ float g_ps2[2 * NC * BATCH];
__device__ float g_psq2[2 * NC * BATCH];
__device__ float g_mean1[NC], g_rstd1[NC];
__device__ float g_mean2[NC], g_rstd2[NC];
__device__ float g_mean3[NC], g_rstd3[NC];
__device__ int g_ctr1 = 0;
__device__ int g_ctr2 = 0;
// pre-split activations (packed bf16x2 hi/lo, [M][K/2] uint32)
__device__ uint32_t g_zh[BATCH * 384],  g_zl[BATCH * 384];
__device__ uint32_t g_z1h[BATCH * 512], g_z1l[BATCH * 512];
__device__ uint32_t g_z2h[BATCH * 256], g_z2l[BATCH * 256];
__device__ float g_z3[BATCH * 128];
// pre-split weights ([K/2][N] uint32)
__device__ uint32_t g_w1h[384 * 1024], g_w1l[384 * 1024];
__device__ uint32_t g_w2h[512 * 512],  g_w2l[512 * 512];
__device__ uint32_t g_w3h[256 * 128],  g_w3l[256 * 128];

// ---------------- helpers ------------------------------------------------------------
__device__ __forceinline__ uint32_t packbf(float x, float y) {
    __nv_bfloat162 p = __floats2bfloat162_rn(x, y);   // x -> low half (even k)
    return *(uint32_t*)&p;
}
__device__ __forceinline__ void splitpack(float x, float y, uint32_t& h, uint32_t& l) {
    __nv_bfloat16 hx = __float2bfloat16_rn(x);
    __nv_bfloat16 hy = __float2bfloat16_rn(y);
    __nv_bfloat162 ph; ph.x = hx; ph.y = hy;
    h = *(uint32_t*)&ph;
    l = packbf(x - __bfloat162float(hx), y - __bfloat162float(hy));
}
__device__ __forceinline__ void mma16(float* c, const uint32_t* a, uint32_t b0, uint32_t b1) {
    asm volatile("mma.sync.aligned.m16n8k16.row.col.f32.bf16.bf16.f32 "
                 "{%0,%1,%2,%3},{%4,%5,%6,%7},{%8,%9},{%0,%1,%2,%3};"
                 : "+f"(c[0]), "+f"(c[1]), "+f"(c[2]), "+f"(c[3])
                 : "r"(a[0]), "r"(a[1]), "r"(a[2]), "r"(a[3]), "r"(b0), "r"(b1));
}
#define LDSM4(r, a) \
    asm volatile("ldmatrix.sync.aligned.m8n8.x4.shared.b16 {%0,%1,%2,%3}, [%4];" \
                 : "=r"((r)[0]), "=r"((r)[1]), "=r"((r)[2]), "=r"((r)[3]) : "r"(a))

// ---------------- 1+2+3. fused [weight pre-split] + [conv+stats+pool] + [BN1 fin] ---
// blocks 0..1023: conv path (one per batch row); last arriving conv block also
// finalizes BN1 stats (threadfence reduction). blocks 1024..3711: weight split.
#define SROW_STRIDE 1048
__global__ void __launch_bounds__(256) k_convfuse(const float* __restrict__ x,
                                                  const float* __restrict__ la_bias,
                                                  const float* __restrict__ la_a,
                                                  const float* __restrict__ la_b,
                                                  const float* __restrict__ fw1,
                                                  const float* __restrict__ fw2,
                                                  const float* __restrict__ fw3) {
    __shared__ float sx[1072];
    __shared__ float sf[NC * 16];
    __shared__ float sb[NC];
    __shared__ float srow[8 * SROW_STRIDE];
    __shared__ int sdone;
    int t = threadIdx.x;

    if (blockIdx.x >= 1024) {
        // ---- weight pre-split path ----
        int idx = (blockIdx.x - 1024) * 256 + t;
        const int T1 = 384 * 1024, T2 = 512 * 512, T3 = 256 * 128;
        float a0, a1;
        uint32_t *H, *L;
        int o;
        if (idx < T1) {
            int p = idx >> 10, n = idx & 1023;
            a0 = fw1[(2 * p) * 1024 + n]; a1 = fw1[(2 * p + 1) * 1024 + n];
            H = g_w1h; L = g_w1l; o = idx;
        } else if (idx < T1 + T2) {
            int r = idx - T1;
            int p = r >> 9, n = r & 511;
            a0 = fw2[(2 * p) * 512 + n]; a1 = fw2[(2 * p + 1) * 512 + n];
            H = g_w2h; L = g_w2l; o = r;
        } else if (idx < T1 + T2 + T3) {
            int r = idx - T1 - T2;
            int p = r >> 7, n = r & 127;
            a0 = fw3[(2 * p) * 128 + n]; a1 = fw3[(2 * p + 1) * 128 + n];
            H = g_w3h; L = g_w3l; o = r;
        } else return;
        uint32_t hh, ll;
        splitpack(a0, a1, hh, ll);
        H[o] = hh; L[o] = ll;
        return;
    }

    // ---- conv path ----
    int b = blockIdx.x;
    int l = t & 31, w = t >> 5;
    for (int i = t; i < NC * 16; i += 256) {
        int c = i >> 4, k = i & 15;
        const float wf = 314.1592653589793f;
        const float c1 = (float)(-0.03 / sqrt(1.0 - 0.03 * 0.03));
        float tt = (float)k / 15.0f;
        float p = tt - la_b[c] / la_a[c];
        float arg = wf * (p - 0.1f);
        sf[i] = 0.08f * expf(c1 * arg) * (-sinf(arg));
    }
    if (t < NC) sb[t] = la_bias[t];
    for (int i = t; i < 1072; i += 256) {
        int xi = i - 16;
        sx[i] = (xi >= 0 && xi < 1024) ? x[b * 1024 + xi] : 0.0f;
    }
    __syncthreads();

    float* my = &srow[w * SROW_STRIDE];
    for (int r = 0; r < 4; r++) {
        int c = w * 4 + r;
        float fw[16];
#pragma unroll
        for (int k = 0; k < 16; k++) fw[k] = sf[c * 16 + k];
        float bias = sb[c];
        float s = 0.0f, sq = 0.0f;
        for (int j = 0; j < 9; j++) {
            int o0 = 4 * l + 128 * j;
            if (o0 > 1040) break;
            float xw[20];
#pragma unroll
            for (int q = 0; q < 5; q++) {
                float4 v = *(const float4*)&sx[o0 + 4 * q];
                xw[4 * q + 0] = v.x; xw[4 * q + 1] = v.y; xw[4 * q + 2] = v.z; xw[4 * q + 3] = v.w;
            }
            float4 ov;
            float* op = (float*)&ov;
#pragma unroll
            for (int q = 0; q < 4; q++) {
                float acc = bias;
#pragma unroll
                for (int k = 0; k < 16; k++) acc += xw[q + k] * fw[k];
                op[q] = acc;
                if (o0 + q < LPRE) { s += acc; sq += acc * acc; }
            }
            *(float4*)&my[o0] = ov;
        }
        __syncwarp();
        for (int i = l; i < LH; i += 32) {
            float v = (my[2 * i] + my[2 * i + 1] + my[2 * i + 2]) * (1.0f / 3.0f);
            g_h[(b * NC + c) * LH + i] = v;
        }
#pragma unroll
        for (int off = 16; off > 0; off >>= 1) {
            s  += __shfl_down_sync(0xffffffffu, s, off);
            sq += __shfl_down_sync(0xffffffffu, sq, off);
        }
        if (l == 0) { g_psA[c * BATCH + b] = s; g_psqA[c * BATCH + b] = sq; }
        __syncwarp();
    }

    // ---- last conv block finalizes BN1 stats ----
    __threadfence();
    if (t == 0) sdone = (atomicAdd(&g_ctr1, 1) == 1023) ? 1 : 0;
    __syncthreads();
    if (sdone) {
#pragma unroll
        for (int r = 0; r < 4; r++) {
            int c = r * 8 + w;
            float s = 0.0f, sq = 0.0f;
#pragma unroll
            for (int j = 0; j < 8; j++) {
                float4 v = __ldcg((const float4*)&g_psA[c * BATCH + l * 32 + j * 4]);
                s += (v.x + v.y) + (v.z + v.w);
                float4 q = __ldcg((const float4*)&g_psqA[c * BATCH + l * 32 + j * 4]);
                sq += (q.x + q.y) + (q.z + q.w);
            }
#pragma unroll
            for (int off = 16; off > 0; off >>= 1) {
                s  += __shfl_down_sync(0xffffffffu, s, off);
                sq += __shfl_down_sync(0xffffffffu, sq, off);
            }
            if (l == 0) {
                float n = (float)BATCH * (float)LPRE;
                float m = s / n;
                float v = sq / n - m * m;
                g_mean1[c] = m;
                g_rstd1[c] = rsqrtf(v + 1e-5f);
            }
        }
        __syncthreads();
        if (t == 0) g_ctr1 = 0;    // reset for next graph replay
    }
}

// ---------------- 4+5. branches + fused BN2/BN3 finalize ----------------------------
__global__ void __launch_bounds__(256) k_branches(
        const float* __restrict__ bn1_g, const float* __restrict__ bn1_b,
        const float* __restrict__ a1_w, const float* __restrict__ a1_b,
        const float* __restrict__ e1_w, const float* __restrict__ e1_b,
        const float* __restrict__ f1_w, const float* __restrict__ f1_b,
        const float* __restrict__ fa_w, const float* __restrict__ fa_b) {
    __shared__ int sdone;
    int t = threadIdx.x;
    int l = t & 31, w = t >> 5;
    int pr = blockIdx.x * 8 + w;
    int b = pr >> 5, c = pr & 31;

    float sc = g_rstd1[c] * bn1_g[c];
    float shv = bn1_b[c] - g_mean1[c] * sc;

    float hw[34];
    {
        const float* row = &g_h[(b * NC + c) * LH + 16 * l];
#pragma unroll
        for (int q = 0; q < 5; q++) {
            float4 v = *(const float4*)&row[4 * q];
            hw[4 * q + 0] = v.x; hw[4 * q + 1] = v.y; hw[4 * q + 2] = v.z; hw[4 * q + 3] = v.w;
        }
    }
#pragma unroll
    for (int q = 0; q < 14; q++)
        hw[20 + q] = __shfl_down_sync(0xffffffffu, hw[4 + q], 1);

#pragma unroll
    for (int br = 0; br < 2; br++) {
        float w1v[8], w2v[8], bias1, bias2;
        if (br == 0) {
            float sw = 0.0f;
#pragma unroll
            for (int k = 0; k < 8; k++) { float wv = a1_w[c * 8 + k]; w1v[k] = sc * wv; sw += wv; }
            bias1 = (a1_b[c] - sw) + shv * sw;                 // Always
#pragma unroll
            for (int k = 0; k < 8; k++) w2v[k] = e1_w[c * 8 + k];
            bias2 = 1.0f - e1_b[c];                            // Eventually
        } else {
            float sw = 0.0f;
#pragma unroll
            for (int k = 0; k < 8; k++) { float wv = f1_w[c * 8 + k]; w1v[k] = sc * wv; sw += wv; }
            bias1 = (1.0f - f1_b[c]) + shv * sw;               // Eventually
            float sw2 = 0.0f;
#pragma unroll
            for (int k = 0; k < 8; k++) { float wv = fa_w[c * 8 + k]; w2v[k] = wv; sw2 += wv; }
            bias2 = fa_b[c] - sw2;                             // Always
        }

        float a[14];
#pragma unroll
        for (int m = 0; m < 14; m++) {
            float acc = bias1;
#pragma unroll
            for (int k = 0; k < 8; k++) acc += hw[2 * m + k] * w1v[k];
            a[m] = fmaxf(acc, 0.0f);
        }
        float mx = 0.0f;
#pragma unroll
        for (int q = 0; q < 4; q++) {
            float e = bias2;
#pragma unroll
            for (int k = 0; k < 8; k++) e += a[2 * q + k] * w2v[k];
            e = fmaxf(e, 0.0f);
            mx = (q == 0) ? e : fmaxf(mx, e);
        }
        float s = 0.0f, sqv = 0.0f;
        if (l < 31) {
            float* pout = (br == 0) ? g_p1 : g_p2;
            pout[(b * NC + c) * LP + l] = mx;
            s = mx; sqv = mx * mx;
        }
#pragma unroll
        for (int off = 16; off > 0; off >>= 1) {
            s   += __shfl_down_sync(0xffffffffu, s, off);
            sqv += __shfl_down_sync(0xffffffffu, sqv, off);
        }
        if (l == 0) {
            g_ps2[(br * NC + c) * BATCH + b] = s;
            g_psq2[(br * NC + c) * BATCH + b] = sqv;
        }
    }

    // ---- last block finalizes BN2/BN3 stats ----
    __threadfence();
    if (t == 0) sdone = (atomicAdd(&g_ctr2, 1) == (int)gridDim.x - 1) ? 1 : 0;
    __syncthreads();
    if (sdone) {
#pragma unroll
        for (int r = 0; r < 8; r++) {
            int bc = r * 8 + w;
            float s = 0.0f, sq = 0.0f;
#pragma unroll
            for (int j = 0; j < 8; j++) {
                float4 v = __ldcg((const float4*)&g_ps2[bc * BATCH + l * 32 + j * 4]);
                s += (v.x + v.y) + (v.z + v.w);
                float4 q = __ldcg((const float4*)&g_psq2[bc * BATCH + l * 32 + j * 4]);
                sq += (q.x + q.y) + (q.z + q.w);
            }
#pragma unroll
            for (int off = 16; off > 0; off >>= 1) {
                s  += __shfl_down_sync(0xffffffffu, s, off);
                sq += __shfl_down_sync(0xffffffffu, sq, off);
            }
            if (l == 0) {
                float n = (float)BATCH * (float)LP;
                float m = s / n;
                float v = sq / n - m * m;
                int brq = bc >> 5, cc = bc & 31;
                if (brq == 0) { g_mean2[cc] = m; g_rstd2[cc] = rsqrtf(v + 1e-5f); }
                else          { g_mean3[cc] = m; g_rstd3[cc] = rsqrtf(v + 1e-5f); }
            }
        }
        __syncthreads();
        if (t == 0) g_ctr2 = 0;    // reset for next graph replay
    }
}

// ---------------- 6. BN + final eventually -> pre-split z ---------------------------
__global__ void __launch_bounds__(256) k_stage2(
        const float* __restrict__ g2, const float* __restrict__ be2,
        const float* __restrict__ w2, const float* __restrict__ bb2,
        const float* __restrict__ g3, const float* __restrict__ be3,
        const float* __restrict__ w3, const float* __restrict__ bb3) {
    int branch = blockIdx.y;
    int bc = blockIdx.x * blockDim.x + threadIdx.x;
    if (bc >= BATCH * NC) return;
    int b = bc >> 5, c = bc & (NC - 1);
    const float *p, *meanv, *rstdv, *g, *be, *w, *bb;
    int zhalf;
    if (branch == 0) { p = g_p1; meanv = g_mean2; rstdv = g_rstd2; zhalf = 0;
                       g = g2; be = be2; w = w2; bb = bb2; }
    else             { p = g_p2; meanv = g_mean3; rstdv = g_rstd3; zhalf = 192;
                       g = g3; be = be3; w = w3; bb = bb3; }
    float sc = rstdv[c] * g[c];
    float sh = be[c] - meanv[c] * sc;
    float wv[8];
    float sw = 0.0f;
#pragma unroll
    for (int k = 0; k < 8; k++) { wv[k] = w[c * 8 + k] * sc; sw += w[c * 8 + k]; }
    float bias = (1.0f - bb[c]) + sh * sw;
    float y[LP];
    const float* row = &p[bc * LP];
#pragma unroll
    for (int i = 0; i < LP; i++) y[i] = row[i];
    int obase = b * 384 + zhalf + c * (LZ / 2);
#pragma unroll
    for (int j2 = 0; j2 < LZ / 2; j2++) {
        float a0 = bias, a1 = bias;
#pragma unroll
        for (int k = 0; k < 8; k++) {
            a0 += y[4 * j2 + k] * wv[k];
            a1 += y[4 * j2 + 2 + k] * wv[k];
        }
        a0 = fmaxf(a0, 0.0f);
        a1 = fmaxf(a1, 0.0f);
        uint32_t hh, ll;
        splitpack(a0, a1, hh, ll);
        g_zh[obase + j2] = hh;
        g_zl[obase + j2] = ll;
    }
}

// ---------------- 7. pre-split bf16 tensor-core GEMM, ldmatrix A-frags --------------
template<int STAGE>
__global__ void __launch_bounds__(256) k_gemm_bf16(const float* __restrict__ bias) {
    constexpr int KP = STAGE == 0 ? 384 : (STAGE == 1 ? 512 : 256);
    constexpr int N  = STAGE == 0 ? 1024 : (STAGE == 1 ? 512 : 128);
    constexpr int BN = STAGE == 0 ? 64 : (STAGE == 1 ? 32 : 16);
    constexpr int TN = BN / 16;
    constexpr int ITERS = KP / 16;
    constexpr int BTH = 4 * BN;

    const uint32_t* Ah = STAGE == 0 ? g_zh  : (STAGE == 1 ? g_z1h : g_z2h);
    const uint32_t* Al = STAGE == 0 ? g_zl  : (STAGE == 1 ? g_z1l : g_z2l);
    const uint32_t* Bh = STAGE == 0 ? g_w1h : (STAGE == 1 ? g_w2h : g_w3h);
    const uint32_t* Bl = STAGE == 0 ? g_w1l : (STAGE == 1 ? g_w2l : g_w3l);

    __shared__ uint32_t As_h[128 * 20], As_l[128 * 20];
    __shared__ uint32_t Bs_h[16 * 72],  Bs_l[16 * 72];

    int tid = threadIdx.x, lane = tid & 31, wid = tid >> 5;
    int gq = lane >> 2, tg = lane & 3;
    int wm = wid >> 1, wn = wid & 1;
    int m0 = blockIdx.y * 128, n0 = blockIdx.x * BN;

    uint32_t asH = (uint32_t)__cvta_generic_to_shared(As_h);
    uint32_t asL = (uint32_t)__cvta_generic_to_shared(As_l);
    uint32_t aoff[2][2];
    {
        int row_sel = lane & 7, quad = lane >> 3;
#pragma unroll
        for (int tm = 0; tm < 2; tm++)
#pragma unroll
            for (int ks = 0; ks < 2; ks++) {
                int row = wm * 32 + tm * 16 + ((quad & 1) << 3) + row_sel;
                int col = ks * 8 + ((quad >> 1) << 2);
                aoff[tm][ks] = (uint32_t)(row * 20 + col) * 4u;
            }
    }

    int am[2], aq[2];
#pragma unroll
    for (int i = 0; i < 2; i++) { int lin = tid + 256 * i; am[i] = lin >> 2; aq[i] = (lin & 3) * 4; }
    bool bact = tid < BTH;
    int bp = tid / (BN / 4);
    int bn4 = (tid % (BN / 4)) * 4;

    float acc[2][TN][4] = {};

    uint4 pah[2], pal[2], pbh = {}, pbl = {};
#pragma unroll
    for (int i = 0; i < 2; i++) {
        pah[i] = *(const uint4*)&Ah[(m0 + am[i]) * KP + aq[i]];
        pal[i] = *(const uint4*)&Al[(m0 + am[i]) * KP + aq[i]];
    }
    if (bact) {
        pbh = *(const uint4*)&Bh[bp * N + n0 + bn4];
        pbl = *(const uint4*)&Bl[bp * N + n0 + bn4];
    }

    for (int it = 0; it < ITERS; it++) {
#pragma unroll
        for (int i = 0; i < 2; i++) {
            *(uint4*)&As_h[am[i] * 20 + aq[i]] = pah[i];
            *(uint4*)&As_l[am[i] * 20 + aq[i]] = pal[i];
        }
        if (bact) {
            *(uint4*)&Bs_h[bp * 72 + bn4] = pbh;
            *(uint4*)&Bs_l[bp * 72 + bn4] = pbl;
        }
        __syncthreads();
        if (it + 1 < ITERS) {
            int kp0 = (it + 1) * 16;
#pragma unroll
            for (int i = 0; i < 2; i++) {
                pah[i] = *(const uint4*)&Ah[(m0 + am[i]) * KP + kp0 + aq[i]];
                pal[i] = *(const uint4*)&Al[(m0 + am[i]) * KP + kp0 + aq[i]];
            }
            if (bact) {
                pbh = *(const uint4*)&Bh[(kp0 + bp) * N + n0 + bn4];
                pbl = *(const uint4*)&Bl[(kp0 + bp) * N + n0 + bn4];
            }
        }
#pragma unroll
        for (int ks = 0; ks < 2; ks++) {
            int kb = ks * 8 + tg;
            uint32_t ah[2][4], al[2][4];
#pragma unroll
            for (int tm = 0; tm < 2; tm++) {
                LDSM4(ah[tm], asH + aoff[tm][ks]);
                LDSM4(al[tm], asL + aoff[tm][ks]);
            }
#pragma unroll
            for (int tn = 0; tn < TN; tn++) {
                int nIdx = wn * (BN / 2) + tn * 8 + gq;
                uint32_t bh0 = Bs_h[kb * 72 + nIdx], bh1 = Bs_h[(kb + 4) * 72 + nIdx];
                uint32_t bl0 = Bs_l[kb * 72 + nIdx], bl1 = Bs_l[(kb + 4) * 72 + nIdx];
#pragma unroll
                for (int tm = 0; tm < 2; tm++) {
                    mma16(acc[tm][tn], ah[tm], bh0, bh1);
                    mma16(acc[tm][tn], ah[tm], bl0, bl1);
                    mma16(acc[tm][tn], al[tm], bh0, bh1);
                }
            }
        }
        __syncthreads();
    }

#pragma unroll
    for (int tm = 0; tm < 2; tm++) {
        int row = m0 + wm * 32 + tm * 16 + gq;
#pragma unroll
        for (int tn = 0; tn < TN; tn++) {
            int col = n0 + wn * (BN / 2) + tn * 8 + tg * 2;
            float bv0 = bias[col], bv1 = bias[col + 1];
            float v0 = fmaxf(acc[tm][tn][0] + bv0, 0.0f);
            float v1 = fmaxf(acc[tm][tn][1] + bv1, 0.0f);
            float v2 = fmaxf(acc[tm][tn][2] + bv0, 0.0f);
            float v3 = fmaxf(acc[tm][tn][3] + bv1, 0.0f);
            if (STAGE < 2) {
                constexpr int KPo = N / 2;
                uint32_t* Ch = STAGE == 0 ? g_z1h : g_z2h;
                uint32_t* Cl = STAGE == 0 ? g_z1l : g_z2l;
                uint32_t hh, ll;
                splitpack(v0, v1, hh, ll);
                Ch[row * KPo + col / 2] = hh;
                Cl[row * KPo + col / 2] = ll;
                splitpack(v2, v3, hh, ll);
                Ch[(row + 8) * KPo + col / 2] = hh;
                Cl[(row + 8) * KPo + col / 2] = ll;
            } else {
                g_z3[row * N + col] = v0;
                g_z3[row * N + col + 1] = v1;
                g_z3[(row + 8) * N + col] = v2;
                g_z3[(row + 8) * N + col + 1] = v3;
            }
        }
    }
}

// ---------------- 8. final tiny GEMM (K=128, N=10) ----------------------------------
__global__ void __launch_bounds__(256) k_gemm4(const float* __restrict__ W,
                                               const float* __restrict__ bias,
                                               float* __restrict__ out) {
    __shared__ float sw[128 * 10];
    __shared__ float sb[10];
    int t = threadIdx.x;
    for (int i = t; i < 1280; i += 256) sw[i] = W[i];
    if (t < 10) sb[t] = bias[t];
    __syncthreads();
    int idx = blockIdx.x * 256 + t;
    if (idx >= BATCH * 10) return;
    int m = idx / 10, n = idx % 10;
    const float* a = &g_z3[m * 128];
    float acc = sb[n];
#pragma unroll 16
    for (int k = 0; k < 128; k++) acc += a[k] * sw[k * 10 + n];
    out[idx] = fmaxf(acc, 0.0f);
}

// ---------------- host ---------------------------------------------------------------
extern "C" void kernel_launch(void* const* d_in, const int* in_sizes, int n_in,
                              void* d_out, int out_size) {
    const float* x       = (const float*)d_in[0];
    const float* la_a    = (const float*)d_in[1];
    const float* la_b    = (const float*)d_in[2];
    const float* la_bias = (const float*)d_in[3];
    const float* bn1_g   = (const float*)d_in[4];
    const float* bn1_b   = (const float*)d_in[5];
    const float* a1_w = (const float*)d_in[6];
    const float* a1_b = (const float*)d_in[7];
    const float* e1_w = (const float*)d_in[8];
    const float* e1_b = (const float*)d_in[9];
    const float* bn2_g = (const float*)d_in[10];
    const float* bn2_b = (const float*)d_in[11];
    const float* e2_w = (const float*)d_in[12];
    const float* e2_b = (const float*)d_in[13];
    const float* f1_w = (const float*)d_in[14];
    const float* f1_b = (const float*)d_in[15];
    const float* fa_w = (const float*)d_in[16];
    const float* fa_b = (const float*)d_in[17];
    const float* bn3_g = (const float*)d_in[18];
    const float* bn3_b = (const float*)d_in[19];
    const float* f2_w = (const float*)d_in[20];
    const float* f2_b = (const float*)d_in[21];
    const float* w1 = (const float*)d_in[22];
    const float* b1 = (const float*)d_in[23];
    const float* w2 = (const float*)d_in[24];
    const float* b2 = (const float*)d_in[25];
    const float* w3 = (const float*)d_in[26];
    const float* b3 = (const float*)d_in[27];
    const float* w4 = (const float*)d_in[28];
    const float* b4 = (const float*)d_in[29];
    float* out = (float*)d_out;

    // conv + weight pre-split + BN1 finalize, one launch
    k_convfuse<<<3712, 256>>>(x, la_bias, la_a, la_b, w1, w2, w3);
    // branches + BN2/BN3 finalize, one launch
    k_branches<<<BATCH * NC / 8, 256>>>(bn1_g, bn1_b, a1_w, a1_b, e1_w, e1_b,
                                        f1_w, f1_b, fa_w, fa_b);
    k_stage2<<<dim3(128, 2), 256>>>(bn2_g, bn2_b, e2_w, e2_b,
                                    bn3_g, bn3_b, f2_w, f2_b);

    k_gemm_bf16<0><<<dim3(16, 8), 256>>>(b1);
    k_gemm_bf16<1><<<dim3(16, 8), 256>>>(b2);
    k_gemm_bf16<2><<<dim3(8, 8),  256>>>(b3);
    k_gemm4<<<40, 256>>>(w4, b4, out);
}

// round 16
// speedup vs baseline: 1.2090x; 1.2090x over previous
#include <cuda_runtime.h>
#include <cuda_bf16.h>
#include <math.h>
#include <stdint.h>

#define BATCH 1024
#define NC 32
#define LPRE 1041
#define LH 520
#define L1 257
#define L2 125
#define LP 31
#define LZ 12

// ---------------- scratch (device globals) ------------------------------------------
__device__ float g_h[BATCH * NC * LH];            // pooled RAW conv (pre-BN), 68 MB
__device__ float g_p1[BATCH * NC * LP];
__device__ float g_p2[BATCH * NC * LP];
__device__ float g_psA[NC * BATCH];
__device__ float g_psqA[NC * BATCH];
__device__ float g_ps2[2 * NC * BATCH];
__device__ float g_psq2[2 * NC * BATCH];
__device__ float g_mean1[NC], g_rstd1[NC];
__device__ float g_mean2[NC], g_rstd2[NC];
__device__ float g_mean3[NC], g_rstd3[NC];
// pre-split activations (packed bf16x2 hi/lo, [M][K/2] uint32)
__device__ uint32_t g_zh[BATCH * 384],  g_zl[BATCH * 384];
__device__ uint32_t g_z1h[BATCH * 512], g_z1l[BATCH * 512];
__device__ uint32_t g_z2h[BATCH * 256], g_z2l[BATCH * 256];
__device__ float g_z3[BATCH * 128];
// pre-split weights ([K/2][N] uint32)
__device__ uint32_t g_w1h[384 * 1024], g_w1l[384 * 1024];
__device__ uint32_t g_w2h[512 * 512],  g_w2l[512 * 512];
__device__ uint32_t g_w3h[256 * 128],  g_w3l[256 * 128];

// ---------------- helpers ------------------------------------------------------------
__device__ __forceinline__ uint32_t packbf(float x, float y) {
    __nv_bfloat162 p = __floats2bfloat162_rn(x, y);   // x -> low half (even k)
    return *(uint32_t*)&p;
}
__device__ __forceinline__ void splitpack(float x, float y, uint32_t& h, uint32_t& l) {
    __nv_bfloat16 hx = __float2bfloat16_rn(x);
    __nv_bfloat16 hy = __float2bfloat16_rn(y);
    __nv_bfloat162 ph; ph.x = hx; ph.y = hy;
    h = *(uint32_t*)&ph;
    l = packbf(x - __bfloat162float(hx), y - __bfloat162float(hy));
}
__device__ __forceinline__ void mma16(float* c, const uint32_t* a, uint32_t b0, uint32_t b1) {
    asm volatile("mma.sync.aligned.m16n8k16.row.col.f32.bf16.bf16.f32 "
                 "{%0,%1,%2,%3},{%4,%5,%6,%7},{%8,%9},{%0,%1,%2,%3};"
                 : "+f"(c[0]), "+f"(c[1]), "+f"(c[2]), "+f"(c[3])
                 : "r"(a[0]), "r"(a[1]), "r"(a[2]), "r"(a[3]), "r"(b0), "r"(b1));
}
#define LDSM4(r, a) \
    asm volatile("ldmatrix.sync.aligned.m8n8.x4.shared.b16 {%0,%1,%2,%3}, [%4];" \
                 : "=r"((r)[0]), "=r"((r)[1]), "=r"((r)[2]), "=r"((r)[3]) : "r"(a))

// ---------------- 1+2. fused [weight pre-split] + [conv + stats + avgpool] ----------
// blocks 0..1023: conv path (one per batch row). blocks 1024..3711: weight split.
#define SROW_STRIDE 1048
__global__ void __launch_bounds__(256) k_convfuse(const float* __restrict__ x,
                                                  const float* __restrict__ la_bias,
                                                  const float* __restrict__ la_a,
                                                  const float* __restrict__ la_b,
                                                  const float* __restrict__ fw1,
                                                  const float* __restrict__ fw2,
                                                  const float* __restrict__ fw3) {
    __shared__ float sx[1072];
    __shared__ float sf[NC * 16];
    __shared__ float sb[NC];
    __shared__ float srow[8 * SROW_STRIDE];
    int t = threadIdx.x;

    if (blockIdx.x >= 1024) {
        // ---- weight pre-split path ----
        int idx = (blockIdx.x - 1024) * 256 + t;
        const int T1 = 384 * 1024, T2 = 512 * 512, T3 = 256 * 128;
        float a0, a1;
        uint32_t *H, *L;
        int o;
        if (idx < T1) {
            int p = idx >> 10, n = idx & 1023;
            a0 = fw1[(2 * p) * 1024 + n]; a1 = fw1[(2 * p + 1) * 1024 + n];
            H = g_w1h; L = g_w1l; o = idx;
        } else if (idx < T1 + T2) {
            int r = idx - T1;
            int p = r >> 9, n = r & 511;
            a0 = fw2[(2 * p) * 512 + n]; a1 = fw2[(2 * p + 1) * 512 + n];
            H = g_w2h; L = g_w2l; o = r;
        } else if (idx < T1 + T2 + T3) {
            int r = idx - T1 - T2;
            int p = r >> 7, n = r & 127;
            a0 = fw3[(2 * p) * 128 + n]; a1 = fw3[(2 * p + 1) * 128 + n];
            H = g_w3h; L = g_w3l; o = r;
        } else return;
        uint32_t hh, ll;
        splitpack(a0, a1, hh, ll);
        H[o] = hh; L[o] = ll;
        return;
    }

    // ---- conv path ----
    int b = blockIdx.x;
    int l = t & 31, w = t >> 5;
    for (int i = t; i < NC * 16; i += 256) {
        int c = i >> 4, k = i & 15;
        const float wf = 314.1592653589793f;
        const float c1 = (float)(-0.03 / sqrt(1.0 - 0.03 * 0.03));
        float tt = (float)k / 15.0f;
        float p = tt - la_b[c] / la_a[c];
        float arg = wf * (p - 0.1f);
        sf[i] = 0.08f * expf(c1 * arg) * (-sinf(arg));
    }
    if (t < NC) sb[t] = la_bias[t];
    for (int i = t; i < 1072; i += 256) {
        int xi = i - 16;
        sx[i] = (xi >= 0 && xi < 1024) ? x[b * 1024 + xi] : 0.0f;
    }
    __syncthreads();

    float* my = &srow[w * SROW_STRIDE];
    for (int r = 0; r < 4; r++) {
        int c = w * 4 + r;
        float fw[16];
#pragma unroll
        for (int k = 0; k < 16; k++) fw[k] = sf[c * 16 + k];
        float bias = sb[c];
        float s = 0.0f, sq = 0.0f;
        for (int j = 0; j < 9; j++) {
            int o0 = 4 * l + 128 * j;
            if (o0 > 1040) break;
            float xw[20];
#pragma unroll
            for (int q = 0; q < 5; q++) {
                float4 v = *(const float4*)&sx[o0 + 4 * q];
                xw[4 * q + 0] = v.x; xw[4 * q + 1] = v.y; xw[4 * q + 2] = v.z; xw[4 * q + 3] = v.w;
            }
            float4 ov;
            float* op = (float*)&ov;
#pragma unroll
            for (int q = 0; q < 4; q++) {
                float acc = bias;
#pragma unroll
                for (int k = 0; k < 16; k++) acc += xw[q + k] * fw[k];
                op[q] = acc;
                if (o0 + q < LPRE) { s += acc; sq += acc * acc; }
            }
            *(float4*)&my[o0] = ov;
        }
        __syncwarp();
        for (int i = l; i < LH; i += 32) {
            float v = (my[2 * i] + my[2 * i + 1] + my[2 * i + 2]) * (1.0f / 3.0f);
            g_h[(b * NC + c) * LH + i] = v;
        }
#pragma unroll
        for (int off = 16; off > 0; off >>= 1) {
            s  += __shfl_down_sync(0xffffffffu, s, off);
            sq += __shfl_down_sync(0xffffffffu, sq, off);
        }
        if (l == 0) { g_psA[c * BATCH + b] = s; g_psqA[c * BATCH + b] = sq; }
        __syncwarp();
    }
}

// ---------------- 3. BN1 finalize ---------------------------------------------------
__global__ void __launch_bounds__(256) k_fin1() {
    int c = blockIdx.x, t = threadIdx.x;
    float s = 0.0f, sq = 0.0f;
    for (int i = t; i < BATCH; i += 256) { s += g_psA[c * BATCH + i]; sq += g_psqA[c * BATCH + i]; }
    __shared__ float ss[256], ssq[256];
    ss[t] = s; ssq[t] = sq;
    __syncthreads();
    for (int o = 128; o > 0; o >>= 1) {
        if (t < o) { ss[t] += ss[t + o]; ssq[t] += ssq[t + o]; }
        __syncthreads();
    }
    if (t == 0) {
        float n = (float)BATCH * (float)LPRE;
        float m = ss[0] / n;
        float v = ssq[0] / n - m * m;
        g_mean1[c] = m;
        g_rstd1[c] = rsqrtf(v + 1e-5f);
    }
}

// ---------------- 4. branches: shuffle-borrowed windows, all-register chain ----------
__global__ void __launch_bounds__(256) k_branches(
        const float* __restrict__ bn1_g, const float* __restrict__ bn1_b,
        const float* __restrict__ a1_w, const float* __restrict__ a1_b,
        const float* __restrict__ e1_w, const float* __restrict__ e1_b,
        const float* __restrict__ f1_w, const float* __restrict__ f1_b,
        const float* __restrict__ fa_w, const float* __restrict__ fa_b) {
    int t = threadIdx.x;
    int l = t & 31, w = t >> 5;
    int pr = blockIdx.x * 8 + w;
    int b = pr >> 5, c = pr & 31;

    float sc = g_rstd1[c] * bn1_g[c];
    float shv = bn1_b[c] - g_mean1[c] * sc;

    float hw[34];
    {
        const float* row = &g_h[(b * NC + c) * LH + 16 * l];
#pragma unroll
        for (int q = 0; q < 5; q++) {
            float4 v = *(const float4*)&row[4 * q];
            hw[4 * q + 0] = v.x; hw[4 * q + 1] = v.y; hw[4 * q + 2] = v.z; hw[4 * q + 3] = v.w;
        }
    }
#pragma unroll
    for (int q = 0; q < 14; q++)
        hw[20 + q] = __shfl_down_sync(0xffffffffu, hw[4 + q], 1);

#pragma unroll
    for (int br = 0; br < 2; br++) {
        float w1v[8], w2v[8], bias1, bias2;
        if (br == 0) {
            float sw = 0.0f;
#pragma unroll
            for (int k = 0; k < 8; k++) { float wv = a1_w[c * 8 + k]; w1v[k] = sc * wv; sw += wv; }
            bias1 = (a1_b[c] - sw) + shv * sw;                 // Always
#pragma unroll
            for (int k = 0; k < 8; k++) w2v[k] = e1_w[c * 8 + k];
            bias2 = 1.0f - e1_b[c];                            // Eventually
        } else {
            float sw = 0.0f;
#pragma unroll
            for (int k = 0; k < 8; k++) { float wv = f1_w[c * 8 + k]; w1v[k] = sc * wv; sw += wv; }
            bias1 = (1.0f - f1_b[c]) + shv * sw;               // Eventually
            float sw2 = 0.0f;
#pragma unroll
            for (int k = 0; k < 8; k++) { float wv = fa_w[c * 8 + k]; w2v[k] = wv; sw2 += wv; }
            bias2 = fa_b[c] - sw2;                             // Always
        }

        float a[14];
#pragma unroll
        for (int m = 0; m < 14; m++) {
            float acc = bias1;
#pragma unroll
            for (int k = 0; k < 8; k++) acc += hw[2 * m + k] * w1v[k];
            a[m] = fmaxf(acc, 0.0f);
        }
        float mx = 0.0f;
#pragma unroll
        for (int q = 0; q < 4; q++) {
            float e = bias2;
#pragma unroll
            for (int k = 0; k < 8; k++) e += a[2 * q + k] * w2v[k];
            e = fmaxf(e, 0.0f);
            mx = (q == 0) ? e : fmaxf(mx, e);
        }
        float s = 0.0f, sqv = 0.0f;
        if (l < 31) {
            float* pout = (br == 0) ? g_p1 : g_p2;
            pout[(b * NC + c) * LP + l] = mx;
            s = mx; sqv = mx * mx;
        }
#pragma unroll
        for (int off = 16; off > 0; off >>= 1) {
            s   += __shfl_down_sync(0xffffffffu, s, off);
            sqv += __shfl_down_sync(0xffffffffu, sqv, off);
        }
        if (l == 0) {
            g_ps2[(br * NC + c) * BATCH + b] = s;
            g_psq2[(br * NC + c) * BATCH + b] = sqv;
        }
    }
}

// ---------------- 5. BN2/BN3 finalize -----------------------------------------------
__global__ void __launch_bounds__(256) k_fin2() {
    int bc = blockIdx.x;
    int t = threadIdx.x;
    float s = 0.0f, sq = 0.0f;
    for (int i = t; i < BATCH; i += 256) { s += g_ps2[bc * BATCH + i]; sq += g_psq2[bc * BATCH + i]; }
    __shared__ float ss[256], ssq[256];
    ss[t] = s; ssq[t] = sq;
    __syncthreads();
    for (int o = 128; o > 0; o >>= 1) {
        if (t < o) { ss[t] += ss[t + o]; ssq[t] += ssq[t + o]; }
        __syncthreads();
    }
    if (t == 0) {
        float n = (float)BATCH * (float)LP;
        float m = ss[0] / n;
        float v = ssq[0] / n - m * m;
        int br = bc >> 5, c = bc & 31;
        if (br == 0) { g_mean2[c] = m; g_rstd2[c] = rsqrtf(v + 1e-5f); }
        else         { g_mean3[c] = m; g_rstd3[c] = rsqrtf(v + 1e-5f); }
    }
}

// ---------------- 6. BN + final eventually -> pre-split z ---------------------------
__global__ void __launch_bounds__(256) k_stage2(
        const float* __restrict__ g2, const float* __restrict__ be2,
        const float* __restrict__ w2, const float* __restrict__ bb2,
        const float* __restrict__ g3, const float* __restrict__ be3,
        const float* __restrict__ w3, const float* __restrict__ bb3) {
    int branch = blockIdx.y;
    int bc = blockIdx.x * blockDim.x + threadIdx.x;
    if (bc >= BATCH * NC) return;
    int b = bc >> 5, c = bc & (NC - 1);
    const float *p, *meanv, *rstdv, *g, *be, *w, *bb;
    int zhalf;
    if (branch == 0) { p = g_p1; meanv = g_mean2; rstdv = g_rstd2; zhalf = 0;
                       g = g2; be = be2; w = w2; bb = bb2; }
    else             { p = g_p2; meanv = g_mean3; rstdv = g_rstd3; zhalf = 192;
                       g = g3; be = be3; w = w3; bb = bb3; }
    float sc = rstdv[c] * g[c];
    float sh = be[c] - meanv[c] * sc;
    float wv[8];
    float sw = 0.0f;
#pragma unroll
    for (int k = 0; k < 8; k++) { wv[k] = w[c * 8 + k] * sc; sw += w[c * 8 + k]; }
    float bias = (1.0f - bb[c]) + sh * sw;
    float y[LP];
    const float* row = &p[bc * LP];
#pragma unroll
    for (int i = 0; i < LP; i++) y[i] = row[i];
    int obase = b * 384 + zhalf + c * (LZ / 2);
#pragma unroll
    for (int j2 = 0; j2 < LZ / 2; j2++) {
        float a0 = bias, a1 = bias;
#pragma unroll
        for (int k = 0; k < 8; k++) {
            a0 += y[4 * j2 + k] * wv[k];
            a1 += y[4 * j2 + 2 + k] * wv[k];
        }
        a0 = fmaxf(a0, 0.0f);
        a1 = fmaxf(a1, 0.0f);
        uint32_t hh, ll;
        splitpack(a0, a1, hh, ll);
        g_zh[obase + j2] = hh;
        g_zl[obase + j2] = ll;
    }
}

// ---------------- 7. pre-split bf16 GEMM: BM=64, 2-buffer pipeline, 1 sync/iter -----
// grid (N/BN, 16). warps 2x4: warp tile 32 x (BN/4). Same k accumulation order as
// before -> bit-identical results; occupancy 2-3 blocks/SM vs 1.
template<int STAGE>
__global__ void __launch_bounds__(256) k_gemm_bf16(const float* __restrict__ bias) {
    constexpr int KP = STAGE == 0 ? 384 : (STAGE == 1 ? 512 : 256);
    constexpr int N  = STAGE == 0 ? 1024 : (STAGE == 1 ? 512 : 128);
    constexpr int BN = STAGE == 2 ? 32 : 64;
    constexpr int TN = BN / 32;              // n-subtiles of 8 per warp
    constexpr int ITERS = KP / 16;
    constexpr int BTH = 16 * BN / 4;         // threads loading B (1 uint4 each)

    const uint32_t* Ah = STAGE == 0 ? g_zh  : (STAGE == 1 ? g_z1h : g_z2h);
    const uint32_t* Al = STAGE == 0 ? g_zl  : (STAGE == 1 ? g_z1l : g_z2l);
    const uint32_t* Bh = STAGE == 0 ? g_w1h : (STAGE == 1 ? g_w2h : g_w3h);
    const uint32_t* Bl = STAGE == 0 ? g_w1l : (STAGE == 1 ? g_w2l : g_w3l);

    __shared__ uint32_t As_h[2][64 * 20], As_l[2][64 * 20];
    __shared__ uint32_t Bs_h[2][16 * 72],  Bs_l[2][16 * 72];

    int tid = threadIdx.x, lane = tid & 31, wid = tid >> 5;
    int gq = lane >> 2, tg = lane & 3;
    int wm = wid >> 2, wn = wid & 3;        // 2 x 4 warps
    int m0 = blockIdx.y * 64, n0 = blockIdx.x * BN;

    uint32_t asH = (uint32_t)__cvta_generic_to_shared(As_h);
    uint32_t asL = (uint32_t)__cvta_generic_to_shared(As_l);
    uint32_t aoff[2][2];
    {
        int row_sel = lane & 7, quad = lane >> 3;
#pragma unroll
        for (int tm = 0; tm < 2; tm++)
#pragma unroll
            for (int ks = 0; ks < 2; ks++) {
                int row = wm * 32 + tm * 16 + ((quad & 1) << 3) + row_sel;
                int col = ks * 8 + ((quad >> 1) << 2);
                aoff[tm][ks] = (uint32_t)(row * 20 + col) * 4u;
            }
    }

    int am = tid >> 2, aq = (tid & 3) * 4;   // A: 64 rows x 16 kp, 1 uint4/thread
    bool bact = tid < BTH;
    int bp = tid / (BN / 4);
    int bn4 = (tid % (BN / 4)) * 4;

    float acc[2][TN][4] = {};

    // preload tile 0
    uint4 pah, pal, pbh = {}, pbl = {};
    pah = *(const uint4*)&Ah[(m0 + am) * KP + aq];
    pal = *(const uint4*)&Al[(m0 + am) * KP + aq];
    if (bact) {
        pbh = *(const uint4*)&Bh[bp * N + n0 + bn4];
        pbl = *(const uint4*)&Bl[bp * N + n0 + bn4];
    }
    *(uint4*)&As_h[0][am * 20 + aq] = pah;
    *(uint4*)&As_l[0][am * 20 + aq] = pal;
    if (bact) {
        *(uint4*)&Bs_h[0][bp * 72 + bn4] = pbh;
        *(uint4*)&Bs_l[0][bp * 72 + bn4] = pbl;
    }
    __syncthreads();

    for (int it = 0; it < ITERS; it++) {
        int buf = it & 1;
        if (it + 1 < ITERS) {
            int kp0 = (it + 1) * 16;
            pah = *(const uint4*)&Ah[(m0 + am) * KP + kp0 + aq];
            pal = *(const uint4*)&Al[(m0 + am) * KP + kp0 + aq];
            if (bact) {
                pbh = *(const uint4*)&Bh[(kp0 + bp) * N + n0 + bn4];
                pbl = *(const uint4*)&Bl[(kp0 + bp) * N + n0 + bn4];
            }
        }
        uint32_t bufA = (uint32_t)(buf * 64 * 20 * 4);
#pragma unroll
        for (int ks = 0; ks < 2; ks++) {
            int kb = ks * 8 + tg;
            uint32_t ah[2][4], al[2][4];
#pragma unroll
            for (int tm = 0; tm < 2; tm++) {
                LDSM4(ah[tm], asH + bufA + aoff[tm][ks]);
                LDSM4(al[tm], asL + bufA + aoff[tm][ks]);
            }
#pragma unroll
            for (int tn = 0; tn < TN; tn++) {
                int nIdx = wn * (TN * 8) + tn * 8 + gq;
                uint32_t bh0 = Bs_h[buf][kb * 72 + nIdx], bh1 = Bs_h[buf][(kb + 4) * 72 + nIdx];
                uint32_t bl0 = Bs_l[buf][kb * 72 + nIdx], bl1 = Bs_l[buf][(kb + 4) * 72 + nIdx];
#pragma unroll
                for (int tm = 0; tm < 2; tm++) {
                    mma16(acc[tm][tn], ah[tm], bh0, bh1);
                    mma16(acc[tm][tn], ah[tm], bl0, bl1);
                    mma16(acc[tm][tn], al[tm], bh0, bh1);
                }
            }
        }
        if (it + 1 < ITERS) {
            int nb = buf ^ 1;
            *(uint4*)&As_h[nb][am * 20 + aq] = pah;
            *(uint4*)&As_l[nb][am * 20 + aq] = pal;
            if (bact) {
                *(uint4*)&Bs_h[nb][bp * 72 + bn4] = pbh;
                *(uint4*)&Bs_l[nb][bp * 72 + bn4] = pbl;
            }
        }
        __syncthreads();
    }

#pragma unroll
    for (int tm = 0; tm < 2; tm++) {
        int row = m0 + wm * 32 + tm * 16 + gq;
#pragma unroll
        for (int tn = 0; tn < TN; tn++) {
            int col = n0 + wn * (TN * 8) + tn * 8 + tg * 2;
            float bv0 = bias[col], bv1 = bias[col + 1];
            float v0 = fmaxf(acc[tm][tn][0] + bv0, 0.0f);
            float v1 = fmaxf(acc[tm][tn][1] + bv1, 0.0f);
            float v2 = fmaxf(acc[tm][tn][2] + bv0, 0.0f);
            float v3 = fmaxf(acc[tm][tn][3] + bv1, 0.0f);
            if (STAGE < 2) {
                constexpr int KPo = N / 2;
                uint32_t* Ch = STAGE == 0 ? g_z1h : g_z2h;
                uint32_t* Cl = STAGE == 0 ? g_z1l : g_z2l;
                uint32_t hh, ll;
                splitpack(v0, v1, hh, ll);
                Ch[row * KPo + col / 2] = hh;
                Cl[row * KPo + col / 2] = ll;
                splitpack(v2, v3, hh, ll);
                Ch[(row + 8) * KPo + col / 2] = hh;
                Cl[(row + 8) * KPo + col / 2] = ll;
            } else {
                g_z3[row * N + col] = v0;
                g_z3[row * N + col + 1] = v1;
                g_z3[(row + 8) * N + col] = v2;
                g_z3[(row + 8) * N + col + 1] = v3;
            }
        }
    }
}

// ---------------- 8. final tiny GEMM (K=128, N=10) ----------------------------------
__global__ void __launch_bounds__(256) k_gemm4(const float* __restrict__ W,
                                               const float* __restrict__ bias,
                                               float* __restrict__ out) {
    __shared__ float sw[128 * 10];
    __shared__ float sb[10];
    int t = threadIdx.x;
    for (int i = t; i < 1280; i += 256) sw[i] = W[i];
    if (t < 10) sb[t] = bias[t];
    __syncthreads();
    int idx = blockIdx.x * 256 + t;
    if (idx >= BATCH * 10) return;
    int m = idx / 10, n = idx % 10;
    const float* a = &g_z3[m * 128];
    float acc = sb[n];
#pragma unroll 16
    for (int k = 0; k < 128; k++) acc += a[k] * sw[k * 10 + n];
    out[idx] = fmaxf(acc, 0.0f);
}

// ---------------- host ---------------------------------------------------------------
extern "C" void kernel_launch(void* const* d_in, const int* in_sizes, int n_in,
                              void* d_out, int out_size) {
    const float* x       = (const float*)d_in[0];
    const float* la_a    = (const float*)d_in[1];
    const float* la_b    = (const float*)d_in[2];
    const float* la_bias = (const float*)d_in[3];
    const float* bn1_g   = (const float*)d_in[4];
    const float* bn1_b   = (const float*)d_in[5];
    const float* a1_w = (const float*)d_in[6];
    const float* a1_b = (const float*)d_in[7];
    const float* e1_w = (const float*)d_in[8];
    const float* e1_b = (const float*)d_in[9];
    const float* bn2_g = (const float*)d_in[10];
    const float* bn2_b = (const float*)d_in[11];
    const float* e2_w = (const float*)d_in[12];
    const float* e2_b = (const float*)d_in[13];
    const float* f1_w = (const float*)d_in[14];
    const float* f1_b = (const float*)d_in[15];
    const float* fa_w = (const float*)d_in[16];
    const float* fa_b = (const float*)d_in[17];
    const float* bn3_g = (const float*)d_in[18];
    const float* bn3_b = (const float*)d_in[19];
    const float* f2_w = (const float*)d_in[20];
    const float* f2_b = (const float*)d_in[21];
    const float* w1 = (const float*)d_in[22];
    const float* b1 = (const float*)d_in[23];
    const float* w2 = (const float*)d_in[24];
    const float* b2 = (const float*)d_in[25];
    const float* w3 = (const float*)d_in[26];
    const float* b3 = (const float*)d_in[27];
    const float* w4 = (const float*)d_in[28];
    const float* b4 = (const float*)d_in[29];
    float* out = (float*)d_out;

    // conv (blocks 0..1023) + weight pre-split (blocks 1024..3711) in ONE launch
    k_convfuse<<<3712, 256>>>(x, la_bias, la_a, la_b, w1, w2, w3);
    k_fin1<<<NC, 256>>>();
    k_branches<<<BATCH * NC / 8, 256>>>(bn1_g, bn1_b, a1_w, a1_b, e1_w, e1_b,
                                        f1_w, f1_b, fa_w, fa_b);
    k_fin2<<<2 * NC, 256>>>();
    k_stage2<<<dim3(128, 2), 256>>>(bn2_g, bn2_b, e2_w, e2_b,
                                    bn3_g, bn3_b, f2_w, f2_b);

    k_gemm_bf16<0><<<dim3(16, 16), 256>>>(b1);
    k_gemm_bf16<1><<<dim3(8, 16),  256>>>(b2);
    k_gemm_bf16<2><<<dim3(4, 16),  256>>>(b3);
    k_gemm4<<<40, 256>>>(w4, b4, out);
}